// round 8
// baseline (speedup 1.0000x reference)
#include <cuda_runtime.h>

#define NTYPES 4
#define NDESC  8
#define KMAX   8
#define LMAX   4
#define MNBR   20
#define RCUT   5.0f
#define PI_F   3.14159265358979f

#define WPB     8                    // atoms (and warps) per block
#define THREADS (WPB * 32)
#define NEDGE   (WPB * MNBR)         // 160 edges per block, pooled across warps 0..4
#define CT_ROWS   (NTYPES * NTYPES)
#define CT_STRIDE 68                 // 68 % 32 == 4; 272B rows keep 16B alignment
#define REC_F4    7                  // 6 float4 used + 1 pad
#define REC_F     (REC_F4 * 4)       // 28 floats = 112B (16B-aligned records)

typedef unsigned long long u64;

__device__ __forceinline__ u64 pk2(float lo, float hi) {
    u64 r; asm("mov.b64 %0,{%1,%2};" : "=l"(r) : "f"(lo), "f"(hi)); return r;
}
__device__ __forceinline__ void upk2(u64 v, float& lo, float& hi) {
    asm("mov.b64 {%0,%1},%2;" : "=f"(lo), "=f"(hi) : "l"(v));
}
__device__ __forceinline__ u64 fma2(u64 a, u64 b, u64 c) {
    u64 d; asm("fma.rn.f32x2 %0,%1,%2,%3;" : "=l"(d) : "l"(a), "l"(b), "l"(c)); return d;
}
__device__ __forceinline__ u64 mul2(u64 a, u64 b) {
    u64 d; asm("mul.rn.f32x2 %0,%1,%2;" : "=l"(d) : "l"(a), "l"(b)); return d;
}

__global__ __launch_bounds__(THREADS)
void angular_desc_kernel(const int*   __restrict__ types,
                         const float* __restrict__ positions,
                         const int*   __restrict__ nbrs,
                         const float* __restrict__ c_table,
                         float*       __restrict__ out,
                         int N)
{
    __shared__ float  sh_ct[CT_ROWS * CT_STRIDE];
    __shared__ float4 sh_e[WPB][MNBR][REC_F4];

    const int tid = threadIdx.x;
    const int A0  = blockIdx.x * WPB;

    // ---- pooled edge assignment: eid in [0,160) handled by warps 0..4 ----
    const int  eid       = tid;
    const bool edge_work = (eid < NEDGE);
    const int  ea  = eid / MNBR;            // atom slot 0..7 within block
    const int  es  = eid % MNBR;            // neighbor slot
    const int  atomE  = A0 + ea;
    const int  clampE = (atomE < N) ? atomE : (N - 1);
    const bool edge_ok = edge_work && (atomE < N);

    // ---------------- issue the FULL dependent gmem chain first ----------------
    int jE = 0, tiE = 0;
    float cx = 0.f, cy = 0.f, cz = 0.f;
    if (edge_work) {
        // coalesced: nbrs row block is contiguous = A0*MNBR + eid
        int nidx = A0 * MNBR + eid;
        int nmax = N * MNBR - 1;
        jE = nbrs[nidx < nmax ? nidx : nmax];
        tiE = types[clampE];
        cx = positions[clampE * 3 + 0];
        cy = positions[clampE * 3 + 1];
        cz = positions[clampE * 3 + 2];
    }
    float ejx = 0.f, ejy = 0.f, ejz = 0.f; int tjE = 0;
    if (edge_work) {
        ejx = positions[jE * 3 + 0];
        ejy = positions[jE * 3 + 1];
        ejz = positions[jE * 3 + 2];
        tjE = types[jE];
    }

    // ---------------- c_table staging: 1 LDG.128 + 1 STS.128 per thread ----------------
    {
        const float4 cv = ((const float4*)c_table)[tid];
        const int row = tid >> 4, col4 = tid & 15;
        *(float4*)&sh_ct[row * CT_STRIDE + col4 * 4] = cv;
    }
    __syncthreads();   // staging visible; also absorbs tail of gmem chain

    // ---------------- Phase 1 (pooled): one edge per active lane ----------------
    if (edge_ok) {
        float dx = ejx - cx, dy = ejy - cy, dz = ejz - cz;
        float n2  = dx * dx + dy * dy + dz * dz;
        float inv = rsqrtf(n2);
        float r   = n2 * inv;
        float x = dx * inv, y = dy * inv, z = dz * inv;

        // Chebyshev radial basis: f_k = (T_k(xc)+1) * 0.5*fc(r)
        float fc  = (r < RCUT) ? (0.5f * __cosf(PI_F * r * (1.0f / RCUT)) + 0.5f) : 0.0f;
        float hfc = 0.5f * fc;
        float xr  = r * (1.0f / RCUT) - 1.0f;
        float xc  = 2.0f * xr * xr - 1.0f;
        float fv[KMAX];
        float tm2 = 1.0f, tm1 = xc;
        fv[0] = (tm2 + 1.0f) * hfc;
        fv[1] = (tm1 + 1.0f) * hfc;
        #pragma unroll
        for (int k = 2; k < KMAX; k++) {
            float t = 2.0f * xc * tm1 - tm2;
            tm2 = tm1; tm1 = t;
            fv[k] = (t + 1.0f) * hfc;
        }

        // packed contraction: g[d] = c_row[d] . fv  via f32x2
        const u64 f01 = pk2(fv[0], fv[1]);
        const u64 f23 = pk2(fv[2], fv[3]);
        const u64 f45 = pk2(fv[4], fv[5]);
        const u64 f67 = pk2(fv[6], fv[7]);
        const float* crow = &sh_ct[(tiE * NTYPES + tjE) * CT_STRIDE];
        float g[NDESC];
        #pragma unroll
        for (int d = 0; d < NDESC; d++) {
            const ulonglong2 cA = *(const ulonglong2*)(crow + d * 8);      // (c0c1)(c2c3)
            const ulonglong2 cB = *(const ulonglong2*)(crow + d * 8 + 4);  // (c4c5)(c6c7)
            u64 acc = mul2(cA.x, f01);
            acc = fma2(cA.y, f23, acc);
            acc = fma2(cB.x, f45, acc);
            acc = fma2(cB.y, f67, acc);
            float lo, hi; upk2(acc, lo, hi);
            g[d] = lo + hi;
        }

        // Real spherical harmonics Z_lm scaled so P_l(u.v) = sum_m Z_lm(u) Z_lm(v)
        float x2 = x * x, y2 = y * y, z2 = z * z;
        const float SQ3  = 1.73205080757f;
        const float SQ3H = 0.86602540378f;
        const float C31  = 0.61237243570f;   // sqrt(6)/4
        const float C32a = 3.87298334621f;   // sqrt(15)
        const float C32b = 1.93649167310f;   // sqrt(15)/2
        const float C33  = 0.79056941504f;   // sqrt(10)/4
        float a5z = 5.0f * z2 - 1.0f;

        sh_e[ea][es][0] = make_float4(g[0], g[1], g[2], g[3]);
        sh_e[ea][es][1] = make_float4(g[4], g[5], g[6], g[7]);
        sh_e[ea][es][2] = make_float4(1.0f, x, y, z);
        sh_e[ea][es][3] = make_float4(SQ3 * x * y, SQ3 * y * z, SQ3 * x * z, SQ3H * (x2 - y2));
        sh_e[ea][es][4] = make_float4(0.5f * (3.0f * z2 - 1.0f),
                                      C33 * y * (3.0f * x2 - y2),
                                      C32a * x * y * z,
                                      C31 * y * a5z);
        sh_e[ea][es][5] = make_float4(0.5f * z * (5.0f * z2 - 3.0f),
                                      C31 * x * a5z,
                                      C32b * z * (x2 - y2),
                                      C33 * x * (x2 - 3.0f * y2));
    }
    __syncthreads();   // records from other warps must be visible

    // ---------------- Phase 2: warp w handles atom A0+w ----------------
    const int warp = tid >> 5;
    const int lane = tid & 31;
    const int atom = A0 + warp;
    if (atom >= N) return;   // whole warp uniform; after all barriers

    const int d  = lane & 7;
    const int mg = lane >> 3;
    const float* rec = (const float*)&sh_e[warp][0][0];

    u64 S01 = 0ull, S23 = 0ull;
    float gg = 0.0f;
    #pragma unroll
    for (int jb = 0; jb < MNBR; jb += 4) {
        float      gv[4];
        ulonglong2 zz[4];
        #pragma unroll
        for (int u = 0; u < 4; u++) {
            const float* base = rec + (jb + u) * REC_F;
            gv[u] = base[d];                                    // broadcast within d-group
            zz[u] = *(const ulonglong2*)(base + 8 + 4 * mg);    // packed (z0z1)(z2z3)
        }
        #pragma unroll
        for (int u = 0; u < 4; u++) {
            u64 gs = pk2(gv[u], gv[u]);
            S01 = fma2(gs, zz[u].x, S01);
            S23 = fma2(gs, zz[u].y, S23);
            gg  = fmaf(gv[u], gv[u], gg);
        }
    }
    float S0, S1, S2, S3;
    upk2(S01, S0, S1);
    upk2(S23, S2, S3);

    // Sums of squares split by l within each m-group:
    // mg0: m0(l0) | m1..3(l1);  mg1: m4..7(l2);  mg2: m8(l2) | m9..11(l3);  mg3: m12..15(l3)
    float PA, PB;
    if (mg == 0 || mg == 2) {
        PA = S0 * S0;
        PB = S1 * S1 + S2 * S2 + S3 * S3;
    } else {
        PA = S0 * S0 + S1 * S1 + S2 * S2 + S3 * S3;
        PB = 0.0f;
    }

    // ---------------- Phase 3: recombine to output lane ----------------
    const int lo = lane & 3;
    const int od = lane >> 2;

    int srcA = (lo == 0) ? od : (lo == 2) ? (8 + od) : (lo == 3) ? (24 + od) : od;
    float vA = __shfl_sync(0xffffffffu, PA, srcA);
    int srcB = (lo == 1) ? od : (16 + od);
    float vB = __shfl_sync(0xffffffffu, PB, srcB);
    float vC = __shfl_sync(0xffffffffu, PA, 16 + od);
    float ggv = __shfl_sync(0xffffffffu, gg, od);

    float sumsq;
    if      (lo == 0) sumsq = vA;
    else if (lo == 1) sumsq = vB;
    else if (lo == 2) sumsq = vA + vC;
    else              sumsq = vA + vB;

    out[atom * (NDESC * LMAX) + lane] = 0.5f * (sumsq - ggv);
}

extern "C" void kernel_launch(void* const* d_in, const int* in_sizes, int n_in,
                              void* d_out, int out_size)
{
    const int*   types     = (const int*)d_in[0];
    const float* positions = (const float*)d_in[1];
    const int*   nbrs      = (const int*)d_in[2];
    const float* c_table   = (const float*)d_in[3];
    float*       out       = (float*)d_out;

    const int N = in_sizes[0];
    const int blocks = (N + WPB - 1) / WPB;
    angular_desc_kernel<<<blocks, THREADS>>>(types, positions, nbrs, c_table, out, N);
}

// round 9
// speedup vs baseline: 1.0300x; 1.0300x over previous
#include <cuda_runtime.h>

#define NTYPES 4
#define NDESC  8
#define KMAX   8
#define LMAX   4
#define MNBR   20
#define RCUT   5.0f
#define PI_F   3.14159265358979f

#define WPB     8
#define THREADS (WPB * 32)
#define CT_ROWS   (NTYPES * NTYPES)
#define CT_STRIDE 68                 // 68 % 32 == 4; 272B rows keep 16B alignment
#define REC_F4    7                  // 6 float4 used + 1 pad
#define REC_F     (REC_F4 * 4)

typedef unsigned long long u64;

__device__ __forceinline__ u64 pk2(float lo, float hi) {
    u64 r; asm("mov.b64 %0,{%1,%2};" : "=l"(r) : "f"(lo), "f"(hi)); return r;
}
__device__ __forceinline__ void upk2(u64 v, float& lo, float& hi) {
    asm("mov.b64 {%0,%1},%2;" : "=f"(lo), "=f"(hi) : "l"(v));
}
__device__ __forceinline__ u64 fma2(u64 a, u64 b, u64 c) {
    u64 d; asm("fma.rn.f32x2 %0,%1,%2,%3;" : "=l"(d) : "l"(a), "l"(b), "l"(c)); return d;
}
__device__ __forceinline__ u64 mul2(u64 a, u64 b) {
    u64 d; asm("mul.rn.f32x2 %0,%1,%2;" : "=l"(d) : "l"(a), "l"(b)); return d;
}

__global__ __launch_bounds__(THREADS)
void angular_desc_kernel(const int*   __restrict__ types,
                         const float* __restrict__ positions,
                         const int*   __restrict__ nbrs,
                         const float* __restrict__ c_table,
                         float*       __restrict__ out,
                         int N)
{
    __shared__ float  sh_ct[CT_ROWS * CT_STRIDE];
    __shared__ float4 sh_e[WPB][MNBR][REC_F4];

    const int tid  = threadIdx.x;
    const int warp = tid >> 5;
    const int lane = tid & 31;
    const int atom = blockIdx.x * WPB + warp;
    const bool valid     = (atom < N);
    const bool edge_lane = valid && (lane < MNBR);

    // ---------------- issue the FULL dependent gmem chain first ----------------
    int j = 0, ti = 0;
    float pix = 0.f, piy = 0.f, piz = 0.f;
    if (valid) {
        ti  = types[atom];
        pix = positions[atom * 3 + 0];
        piy = positions[atom * 3 + 1];
        piz = positions[atom * 3 + 2];
    }
    if (edge_lane) j = nbrs[atom * MNBR + lane];

    float ejx = 0.f, ejy = 0.f, ejz = 0.f; int tj = 0;
    if (edge_lane) {
        ejx = positions[j * 3 + 0];
        ejy = positions[j * 3 + 1];
        ejz = positions[j * 3 + 2];
        tj  = types[j];
    }

    // ---------------- c_table staging: 1 LDG.128 + 1 STS.128 per thread ----------------
    {
        const float4 cv = ((const float4*)c_table)[tid];
        const int row = tid >> 4, col4 = tid & 15;
        *(float4*)&sh_ct[row * CT_STRIDE + col4 * 4] = cv;
    }
    __syncthreads();   // barrier wait absorbs tail of gmem chain

    if (!valid) return;

    // ---------------- Phase 1: per-edge records (lanes 0..19): g[8] and Z[16] ----------------
    if (edge_lane) {
        float dx = ejx - pix;
        float dy = ejy - piy;
        float dz = ejz - piz;

        float n2  = dx * dx + dy * dy + dz * dz;
        float inv = rsqrtf(n2);
        float r   = n2 * inv;
        float x = dx * inv, y = dy * inv, z = dz * inv;

        // Chebyshev radial basis: f_k = (T_k(xc)+1) * 0.5*fc(r)
        float fc  = (r < RCUT) ? (0.5f * __cosf(PI_F * r * (1.0f / RCUT)) + 0.5f) : 0.0f;
        float hfc = 0.5f * fc;
        float xr  = r * (1.0f / RCUT) - 1.0f;
        float xc  = 2.0f * xr * xr - 1.0f;
        float fv[KMAX];
        float tm2 = 1.0f, tm1 = xc;
        fv[0] = (tm2 + 1.0f) * hfc;
        fv[1] = (tm1 + 1.0f) * hfc;
        #pragma unroll
        for (int k = 2; k < KMAX; k++) {
            float t = 2.0f * xc * tm1 - tm2;
            tm2 = tm1; tm1 = t;
            fv[k] = (t + 1.0f) * hfc;
        }

        // packed contraction: g[d] = c_row[d] . fv  via f32x2
        const u64 f01 = pk2(fv[0], fv[1]);
        const u64 f23 = pk2(fv[2], fv[3]);
        const u64 f45 = pk2(fv[4], fv[5]);
        const u64 f67 = pk2(fv[6], fv[7]);
        const float* crow = &sh_ct[(ti * NTYPES + tj) * CT_STRIDE];
        float g[NDESC];
        #pragma unroll
        for (int d = 0; d < NDESC; d++) {
            const ulonglong2 cA = *(const ulonglong2*)(crow + d * 8);      // (c0c1)(c2c3)
            const ulonglong2 cB = *(const ulonglong2*)(crow + d * 8 + 4);  // (c4c5)(c6c7)
            u64 acc = mul2(cA.x, f01);
            acc = fma2(cA.y, f23, acc);
            acc = fma2(cB.x, f45, acc);
            acc = fma2(cB.y, f67, acc);
            float lo, hi; upk2(acc, lo, hi);
            g[d] = lo + hi;
        }

        // Real spherical harmonics Z_lm scaled so P_l(u.v) = sum_m Z_lm(u) Z_lm(v)
        float x2 = x * x, y2 = y * y, z2 = z * z;
        const float SQ3  = 1.73205080757f;
        const float SQ3H = 0.86602540378f;
        const float C31  = 0.61237243570f;   // sqrt(6)/4
        const float C32a = 3.87298334621f;   // sqrt(15)
        const float C32b = 1.93649167310f;   // sqrt(15)/2
        const float C33  = 0.79056941504f;   // sqrt(10)/4
        float a5z = 5.0f * z2 - 1.0f;

        sh_e[warp][lane][0] = make_float4(g[0], g[1], g[2], g[3]);
        sh_e[warp][lane][1] = make_float4(g[4], g[5], g[6], g[7]);
        sh_e[warp][lane][2] = make_float4(1.0f, x, y, z);
        sh_e[warp][lane][3] = make_float4(SQ3 * x * y, SQ3 * y * z, SQ3 * x * z, SQ3H * (x2 - y2));
        sh_e[warp][lane][4] = make_float4(0.5f * (3.0f * z2 - 1.0f),
                                          C33 * y * (3.0f * x2 - y2),
                                          C32a * x * y * z,
                                          C31 * y * a5z);
        sh_e[warp][lane][5] = make_float4(0.5f * z * (5.0f * z2 - 3.0f),
                                          C31 * x * a5z,
                                          C32b * z * (x2 - y2),
                                          C33 * x * (x2 - 3.0f * y2));
    }
    __syncwarp();

    // ---------------- Phase 2: S[d][m] = sum_j g_d(j) Z_m(j) (packed f32x2) ----------------
    const int d  = lane & 7;
    const int mg = lane >> 3;
    const float* rec = (const float*)&sh_e[warp][0][0];

    u64 S01 = 0ull, S23 = 0ull;
    float gg = 0.0f;
    #pragma unroll
    for (int jb = 0; jb < MNBR; jb += 4) {
        float      gv[4];
        ulonglong2 zz[4];
        #pragma unroll
        for (int u = 0; u < 4; u++) {
            const float* base = rec + (jb + u) * REC_F;
            gv[u] = base[d];                                    // broadcast within d-group
            zz[u] = *(const ulonglong2*)(base + 8 + 4 * mg);    // packed (z0z1)(z2z3)
        }
        #pragma unroll
        for (int u = 0; u < 4; u++) {
            u64 gs = pk2(gv[u], gv[u]);
            S01 = fma2(gs, zz[u].x, S01);
            S23 = fma2(gs, zz[u].y, S23);
            gg  = fmaf(gv[u], gv[u], gg);
        }
    }
    float S0, S1, S2, S3;
    upk2(S01, S0, S1);
    upk2(S23, S2, S3);

    // Sums of squares split by l within each m-group:
    // mg0: m0(l0) | m1..3(l1);  mg1: m4..7(l2);  mg2: m8(l2) | m9..11(l3);  mg3: m12..15(l3)
    float PA, PB;
    if (mg == 0 || mg == 2) {
        PA = S0 * S0;
        PB = S1 * S1 + S2 * S2 + S3 * S3;
    } else {
        PA = S0 * S0 + S1 * S1 + S2 * S2 + S3 * S3;
        PB = 0.0f;
    }

    // ---------------- Phase 3: recombine to output lane ----------------
    const int lo = lane & 3;
    const int od = lane >> 2;

    int srcA = (lo == 0) ? od : (lo == 2) ? (8 + od) : (lo == 3) ? (24 + od) : od;
    float vA = __shfl_sync(0xffffffffu, PA, srcA);
    int srcB = (lo == 1) ? od : (16 + od);
    float vB = __shfl_sync(0xffffffffu, PB, srcB);
    float vC = __shfl_sync(0xffffffffu, PA, 16 + od);
    float ggv = __shfl_sync(0xffffffffu, gg, od);

    float sumsq;
    if      (lo == 0) sumsq = vA;
    else if (lo == 1) sumsq = vB;
    else if (lo == 2) sumsq = vA + vC;
    else              sumsq = vA + vB;

    out[atom * (NDESC * LMAX) + lane] = 0.5f * (sumsq - ggv);
}

extern "C" void kernel_launch(void* const* d_in, const int* in_sizes, int n_in,
                              void* d_out, int out_size)
{
    const int*   types     = (const int*)d_in[0];
    const float* positions = (const float*)d_in[1];
    const int*   nbrs      = (const int*)d_in[2];
    const float* c_table   = (const float*)d_in[3];
    float*       out       = (float*)d_out;

    const int N = in_sizes[0];
    const int blocks = (N + WPB - 1) / WPB;
    angular_desc_kernel<<<blocks, THREADS>>>(types, positions, nbrs, c_table, out, N);
}